// round 17
// baseline (speedup 1.0000x reference)
#include <cuda_runtime.h>
#include <cuda_bf16.h>
#include <cstdint>

// Problem constants (fixed shapes from reference)
#define PB 4
#define PT 2048
#define PD 1024
#define PH 16
#define PDH 64
#define PM (PB*PT)          // 8192 rows
#define PN 1024             // H*Dh == D
#define PK 1024

// ---------------- scratch (device globals; no allocations allowed) ----------
__device__ __nv_bfloat16 g_xh [PM*PK];
__device__ __nv_bfloat16 g_wqh[PN*PK];
__device__ __nv_bfloat16 g_wkh[PN*PK];
__device__ __nv_bfloat16 g_wvh[PN*PK];
__device__ __nv_bfloat16 g_oth[PD*PN];
__device__ __nv_bfloat16 g_qh [PM*PN];
__device__ __nv_bfloat16 g_kh [PM*PN];
__device__ __nv_bfloat16 g_vh [PM*PN];
__device__ __nv_bfloat16 g_corr[PM*PN];     // normalized E*V correction (bf16)
__device__ float g_invl[PM*PH];             // per-(row,h) 1/l
__device__ float g_w1[PB*PH*PD];            // W1[b,h][d] = sumv[b,h] . WO[h][d][:]
__device__ float g_xsump[PB*8*PD];          // partial column sums of x

// ======================= PTX helpers (baseline sm_80+ features) =============
__device__ __forceinline__ uint32_t smem_to_u32(const void* p) {
    uint32_t a;
    asm("{ .reg .u64 t; cvta.to.shared.u64 t, %1; cvt.u32.u64 %0, t; }"
        : "=r"(a) : "l"(p));
    return a;
}
__device__ __forceinline__ void cp_async16(uint32_t dst, const void* src) {
    asm volatile("cp.async.cg.shared.global [%0], [%1], 16;"
                 :: "r"(dst), "l"(src) : "memory");
}
#define CP_COMMIT() asm volatile("cp.async.commit_group;" ::: "memory")
#define CP_WAIT0()  asm volatile("cp.async.wait_group 0;" ::: "memory")
#define CP_WAIT1()  asm volatile("cp.async.wait_group 1;" ::: "memory")
#define CP_WAIT2()  asm volatile("cp.async.wait_group 2;" ::: "memory")

__device__ __forceinline__ void ldsm_x4(uint32_t* r, uint32_t addr) {
    asm volatile("ldmatrix.sync.aligned.m8n8.x4.shared.b16 {%0,%1,%2,%3}, [%4];"
                 : "=r"(r[0]), "=r"(r[1]), "=r"(r[2]), "=r"(r[3]) : "r"(addr));
}
__device__ __forceinline__ void ldsm_x4_t(uint32_t* r, uint32_t addr) {
    asm volatile("ldmatrix.sync.aligned.m8n8.x4.trans.shared.b16 {%0,%1,%2,%3}, [%4];"
                 : "=r"(r[0]), "=r"(r[1]), "=r"(r[2]), "=r"(r[3]) : "r"(addr));
}
__device__ __forceinline__ void mma_bf16(float* d, const uint32_t* a, const uint32_t* b) {
    asm volatile("mma.sync.aligned.m16n8k16.row.col.f32.bf16.bf16.f32 "
                 "{%0,%1,%2,%3}, {%4,%5,%6,%7}, {%8,%9}, {%0,%1,%2,%3};"
                 : "+f"(d[0]), "+f"(d[1]), "+f"(d[2]), "+f"(d[3])
                 : "r"(a[0]), "r"(a[1]), "r"(a[2]), "r"(a[3]), "r"(b[0]), "r"(b[1]));
}
__device__ __forceinline__ float fast_ex2(float x) {
    float y;
    asm("ex2.approx.f32 %0, %1;" : "=f"(y) : "f"(x));
    return y;
}
__device__ __forceinline__ uint32_t pack_bf16x2(float lo, float hi) {
    uint32_t r;
    asm("cvt.rn.bf16x2.f32 %0, %1, %2;" : "=r"(r) : "f"(hi), "f"(lo));
    return r;
}

// ---------------- fused setup: bf16 conversions + WO transpose + xsum ------
__global__ __launch_bounds__(256)
void setup_all(const float* __restrict__ x,
               const float* __restrict__ WQ, const float* __restrict__ WK,
               const float* __restrict__ WV, const float* __restrict__ WO,
               __nv_bfloat16* __restrict__ xh,
               __nv_bfloat16* __restrict__ wqh,
               __nv_bfloat16* __restrict__ wkh,
               __nv_bfloat16* __restrict__ wvh,
               __nv_bfloat16* __restrict__ oth,
               float* __restrict__ xsump) {
    const int blk = blockIdx.x;
    if (blk < 11264) {
        const float* src; __nv_bfloat16* hi; int i;
        if (blk < 8192)       { src = x;  hi = xh;  i = blk * 256 + threadIdx.x; }
        else if (blk < 9216)  { src = WQ; hi = wqh; i = (blk - 8192) * 256 + threadIdx.x; }
        else if (blk < 10240) { src = WK; hi = wkh; i = (blk - 9216) * 256 + threadIdx.x; }
        else                  { src = WV; hi = wvh; i = (blk - 10240) * 256 + threadIdx.x; }
        float4 v = ((const float4*)src)[i];
        ((__nv_bfloat162*)hi)[2*i]   = __nv_bfloat162(__float2bfloat16(v.x), __float2bfloat16(v.y));
        ((__nv_bfloat162*)hi)[2*i+1] = __nv_bfloat162(__float2bfloat16(v.z), __float2bfloat16(v.w));
    } else if (blk < 15360) {
        // WO transpose: [H][D][Dh] -> [D][H*Dh] (bf16)
        int idx = (blk - 11264) * 256 + threadIdx.x;
        int k = idx & 63;
        int d = (idx >> 6) & 1023;
        int h = idx >> 16;
        oth[d * 1024 + h * 64 + k] = __float2bfloat16(WO[idx]);
    } else {
        // per-batch column partial sums of x (fp32 exact)
        const int bb = blk - 15360;                // 0..31
        const int b = bb >> 3, slice = bb & 7;
        const int t0 = slice * 256;
        const float* xb = x + (size_t)b * PT * PD;
#pragma unroll
        for (int u = 0; u < 4; u++) {
            const int col = u * 256 + threadIdx.x;
            float s = 0.f;
            for (int t = t0; t < t0 + 256; t++) s += xb[(size_t)t * PD + col];
            xsump[(size_t)bb * PD + col] = s;
        }
    }
}

// ---------------- sumv + W1 fused (all exact fp32, sumv stays in smem) ------
// sumv[b,h,k] = colsum(x)[b] . WV[h][k][:] + T*bV;  W1[b,h][d] = sumv . WO[h][d][:]
__global__ __launch_bounds__(256)
void sumv_w1(const float* __restrict__ xsump, const float* __restrict__ WV,
             const float* __restrict__ bV, const float* __restrict__ WO,
             float* __restrict__ W1) {
    const int bh = blockIdx.x;             // 64
    const int b = bh >> 4, h = bh & 15;
    __shared__ float xs[PD];
    __shared__ float red[256];
    __shared__ float sv[64];
    for (int i = threadIdx.x; i < PD; i += 256) {
        float s = 0.f;
#pragma unroll
        for (int p = 0; p < 8; p++) s += xsump[((b * 8 + p) << 10) + i];
        xs[i] = s;
    }
    __syncthreads();
    const int k = threadIdx.x & 63, part = threadIdx.x >> 6;   // 4 threads/k
    {
        const float* wv = WV + ((size_t)h * PDH + k) * PD + part * 256;
        float s = 0.f;
#pragma unroll 8
        for (int d = 0; d < 256; d++) s += xs[part * 256 + d] * wv[d];
        red[threadIdx.x] = s;
    }
    __syncthreads();
    if (part == 0)
        sv[k] = red[k] + red[64 + k] + red[128 + k] + red[192 + k]
                + 2048.f * bV[h * PDH + k];
    __syncthreads();
    for (int d = threadIdx.x; d < PD; d += 256) {
        const float* wo = WO + ((size_t)h * PD + d) * PDH;
        float s = 0.f;
#pragma unroll
        for (int kk = 0; kk < 64; kk++) s += sv[kk] * wo[kk];
        W1[bh * PD + d] = s;
    }
}

// ---------------- 1-term bf16 NT GEMM via mma.sync --------------------------
// CTA 128x128, BK=64, 3-stage cp.async pipeline, 8 warps 64x32, 2 CTAs/SM.
// LDS_ROW=144: 8 consecutive rows span all 32 banks once -> conflict-free ldsm.
#define LDS_ROW 144
#define TILE_B  (128 * LDS_ROW)          // 18432
#define STAGE_B (2 * TILE_B)             // 36864
#define GEMM_SMEM (3 * STAGE_B)          // 110592

#define GEMM_LOAD(IT) do {                                                      \
        const int k0_ = (IT) * 64;                                              \
        const uint32_t st_ = sdst + (uint32_t)(((IT) % 3) * STAGE_B);           \
        cp_async16(st_ + 0*TILE_B +  0, Ah + aoff + k0_);                       \
        cp_async16(st_ + 0*TILE_B + 16, Ah + aoff + k0_ + 8);                   \
        cp_async16(st_ + 0*TILE_B + 32, Ah + aoff + k0_ + 16);                  \
        cp_async16(st_ + 0*TILE_B + 48, Ah + aoff + k0_ + 24);                  \
        cp_async16(st_ + 1*TILE_B +  0, Bh + boff + k0_);                       \
        cp_async16(st_ + 1*TILE_B + 16, Bh + boff + k0_ + 8);                   \
        cp_async16(st_ + 1*TILE_B + 32, Bh + boff + k0_ + 16);                  \
        cp_async16(st_ + 1*TILE_B + 48, Bh + boff + k0_ + 24);                  \
    } while (0)

#define GEMM_BODY()                                                              \
    extern __shared__ char sm_raw[];                                             \
    const uint32_t sbase = smem_to_u32(sm_raw);                                  \
    const int tid = threadIdx.x;                                                 \
    const int lane = tid & 31, wid = tid >> 5;                                   \
    const int wm = wid & 1, wn = wid >> 1;                                       \
    const int row0 = blockIdx.y * 128, col0 = blockIdx.x * 128;                  \
    const int lrow = tid >> 1, lhalf = tid & 1;                                  \
    const size_t aoff = (size_t)(row0 + lrow) * PK + lhalf * 32;                 \
    const size_t boff = (size_t)(col0 + lrow) * PK + lhalf * 32;                 \
    const uint32_t sdst = sbase + lrow * LDS_ROW + lhalf * 64;                   \
    float acc[4][4][4];                                                          \
    _Pragma("unroll") for (int i = 0; i < 4; i++)                                \
    _Pragma("unroll") for (int j = 0; j < 4; j++)                                \
    _Pragma("unroll") for (int v = 0; v < 4; v++) acc[i][j][v] = 0.f;            \
    GEMM_LOAD(0); CP_COMMIT();                                                   \
    GEMM_LOAD(1); CP_COMMIT();                                                   \
    const int NIT = PK / 64;                                                     \
    for (int it = 0; it < NIT; it++) {                                           \
        CP_WAIT1();                                                              \
        __syncthreads();                                                         \
        if (it + 2 < NIT) GEMM_LOAD(it + 2);                                     \
        CP_COMMIT();                                                             \
        const uint32_t st = sbase + (uint32_t)((it % 3) * STAGE_B);              \
        _Pragma("unroll")                                                        \
        for (int ks = 0; ks < 4; ks++) {                                         \
            const uint32_t kb = ks * 32;                                         \
            uint32_t ah[4][4];                                                   \
            _Pragma("unroll")                                                    \
            for (int mt = 0; mt < 4; mt++) {                                     \
                uint32_t addr = st +                                             \
                    (uint32_t)((wm * 64 + mt * 16 + (lane & 15)) * LDS_ROW) +    \
                    kb + ((lane >> 4) << 4);                                     \
                ldsm_x4(ah[mt], addr);                                           \
            }                                                                    \
            uint32_t bh[4][2];                                                   \
            _Pragma("unroll")                                                    \
            for (int np = 0; np < 2; np++) {                                     \
                uint32_t addr = st + TILE_B +                                    \
                    (uint32_t)((wn * 32 + np * 16 + (lane & 7) + ((lane >> 4) << 3)) * LDS_ROW) + \
                    (((lane >> 3) & 1) << 4) + kb;                               \
                uint32_t r[4];                                                   \
                ldsm_x4(r, addr);                                                \
                bh[2*np][0] = r[0]; bh[2*np][1] = r[1];                          \
                bh[2*np+1][0] = r[2]; bh[2*np+1][1] = r[3];                      \
            }                                                                    \
            _Pragma("unroll")                                                    \
            for (int mt = 0; mt < 4; mt++)                                       \
            _Pragma("unroll")                                                    \
                for (int nt = 0; nt < 4; nt++)                                   \
                    mma_bf16(acc[mt][nt], ah[mt], bh[nt]);                       \
        }                                                                        \
    }

// fused QKV: blockIdx.z selects weight/bias/output (all 1-term, hi output).
// Q pre-scaled by log2(e)/sqrt(Dh) so flash can use raw ex2.
#define QSCALE (0.125f * 1.44269504088896f)
__global__ __launch_bounds__(256, 2)
void gemm_qkv(const __nv_bfloat16* __restrict__ Ah,
              const __nv_bfloat16* __restrict__ wqh,
              const __nv_bfloat16* __restrict__ wkh,
              const __nv_bfloat16* __restrict__ wvh,
              const float* __restrict__ bQ, const float* __restrict__ bK,
              const float* __restrict__ bV,
              __nv_bfloat16* __restrict__ qh,
              __nv_bfloat16* __restrict__ kh,
              __nv_bfloat16* __restrict__ vh) {
    const int z = blockIdx.z;
    const __nv_bfloat16* Bh = (z == 0) ? wqh : (z == 1) ? wkh : wvh;
    const float* bias = (z == 0) ? bQ : (z == 1) ? bK : bV;
    __nv_bfloat16* Ch = (z == 0) ? qh : (z == 1) ? kh : vh;
    const float scale = (z == 0) ? QSCALE : 1.0f;
    GEMM_BODY()
    const int frow = lane >> 2, fcol = 2 * (lane & 3);
#pragma unroll
    for (int mt = 0; mt < 4; mt++) {
#pragma unroll
        for (int nt = 0; nt < 4; nt++) {
            const int gr = row0 + wm * 64 + mt * 16 + frow;
            const int gc = col0 + wn * 32 + nt * 8 + fcol;
            float2 bb = *(const float2*)(bias + gc);
            *(uint32_t*)(Ch + (size_t)gr * PN + gc) =
                pack_bf16x2(scale * (acc[mt][nt][0] + bb.x), scale * (acc[mt][nt][1] + bb.y));
            *(uint32_t*)(Ch + (size_t)(gr + 8) * PN + gc) =
                pack_bf16x2(scale * (acc[mt][nt][2] + bb.x), scale * (acc[mt][nt][3] + bb.y));
        }
    }
}

// O projection: out = corr * WOt^T (1-term bf16) + sum_h invl*W1 (exact fp32).
__global__ __launch_bounds__(256, 2)
void gemm_out(const __nv_bfloat16* __restrict__ Ah,   // corr
              const __nv_bfloat16* __restrict__ Bh,   // WOt hi
              const float* __restrict__ bias,
              const float* __restrict__ invl, const float* __restrict__ W1,
              float* __restrict__ C) {
    GEMM_BODY()

    // ---- epilogue: stage W1 [16][128] and invl [128][17] in smem
    CP_WAIT0();
    __syncthreads();
    float* W1s = (float*)sm_raw;                 // [16][128]
    float* ivs = (float*)(sm_raw + 8192);        // [128][17] padded
    const int bsel = row0 >> 11;                 // batch (row0 multiple of 128)
    for (int i = tid * 4; i < 2048; i += 1024) {
        const int h = i >> 7, c = i & 127;
        *(float4*)&W1s[h * 128 + c] = *(const float4*)&W1[(bsel * 16 + h) * PD + col0 + c];
    }
    for (int i = tid * 4; i < 2048; i += 1024) {
        const int r = i >> 4, h = i & 15;
        float4 v = *(const float4*)&invl[(size_t)(row0 + r) * PH + h];
        ivs[r * 17 + h + 0] = v.x; ivs[r * 17 + h + 1] = v.y;
        ivs[r * 17 + h + 2] = v.z; ivs[r * 17 + h + 3] = v.w;
    }
    __syncthreads();

    const int frow = lane >> 2, fcol = 2 * (lane & 3);
    // add sum_h invl[row][h] * W1[h][col] into acc
#pragma unroll
    for (int h = 0; h < 16; h++) {
        float iv[4][2], wv[4][2];
#pragma unroll
        for (int mt = 0; mt < 4; mt++) {
            const int rl = wm * 64 + mt * 16 + frow;
            iv[mt][0] = ivs[rl * 17 + h];
            iv[mt][1] = ivs[(rl + 8) * 17 + h];
        }
#pragma unroll
        for (int nt = 0; nt < 4; nt++) {
            const int cl = wn * 32 + nt * 8 + fcol;
            wv[nt][0] = W1s[h * 128 + cl];
            wv[nt][1] = W1s[h * 128 + cl + 1];
        }
#pragma unroll
        for (int mt = 0; mt < 4; mt++)
#pragma unroll
            for (int nt = 0; nt < 4; nt++) {
                acc[mt][nt][0] += iv[mt][0] * wv[nt][0];
                acc[mt][nt][1] += iv[mt][0] * wv[nt][1];
                acc[mt][nt][2] += iv[mt][1] * wv[nt][0];
                acc[mt][nt][3] += iv[mt][1] * wv[nt][1];
            }
    }

#pragma unroll
    for (int mt = 0; mt < 4; mt++) {
#pragma unroll
        for (int nt = 0; nt < 4; nt++) {
            const int gr = row0 + wm * 64 + mt * 16 + frow;
            const int gc = col0 + wn * 32 + nt * 8 + fcol;
            float2 bb = *(const float2*)(bias + gc);
            *(float2*)(C + (size_t)gr * PN + gc) =
                make_float2(acc[mt][nt][0] + bb.x, acc[mt][nt][1] + bb.y);
            *(float2*)(C + (size_t)(gr + 8) * PN + gc) =
                make_float2(acc[mt][nt][2] + bb.x, acc[mt][nt][3] + bb.y);
        }
    }
}

// ---------------- flash attention on tensor cores -------------------------
// P = 1 + E, 1-term S. 128-key stages (two 64-key subtiles per barrier).
// Writes corr (bf16) and invl; O projection reconstructs invl*W1 + corr*WOt.
#define FLS_STAGE 32768
#define FLS_QB    16384
#define FLS_SMEM  (FLS_QB + 3 * FLS_STAGE)   // 114688

__global__ __launch_bounds__(256, 2)
void flash_mma(const __nv_bfloat16* __restrict__ Qh,
               const __nv_bfloat16* __restrict__ Kh,
               const __nv_bfloat16* __restrict__ Vh,
               __nv_bfloat16* __restrict__ Corr, float* __restrict__ Invl) {
    extern __shared__ char sm_raw[];
    const uint32_t sb = smem_to_u32(sm_raw);
    const int tid = threadIdx.x, lane = tid & 31, wid = tid >> 5;
    const int q0 = blockIdx.x * 128;
    const int b = blockIdx.y >> 4, h = blockIdx.y & 15;
    const size_t base = (size_t)b * (PT * PN) + (size_t)h * PDH;

    const int lr = tid >> 2;
    const int lc16 = 2 * (tid & 3);
    const __nv_bfloat16* gkh = Kh + base + (size_t)lr * PN + lc16 * 8;
    const __nv_bfloat16* gvh = Vh + base + (size_t)lr * PN + lc16 * 8;
    const uint32_t sw0 = (uint32_t)(((lc16 + 0) ^ (lr & 7)) << 4);
    const uint32_t sw1 = (uint32_t)(((lc16 + 1) ^ (lr & 7)) << 4);
    const uint32_t ldkv = sb + FLS_QB + lr * 128;

// one stage = 128 keys: {K0|V0|K1|V1} of 8KB each
#define LOAD_STAGE(IT) do {                                                     \
        const uint32_t st_ = ldkv + (uint32_t)(((IT) % 3) * FLS_STAGE);         \
        const size_t go_ = (size_t)(IT) * 128 * PN;                             \
        cp_async16(st_ +     0 + sw0, gkh + go_);                               \
        cp_async16(st_ +     0 + sw1, gkh + go_ + 8);                           \
        cp_async16(st_ +  8192 + sw0, gvh + go_);                               \
        cp_async16(st_ +  8192 + sw1, gvh + go_ + 8);                           \
        cp_async16(st_ + 16384 + sw0, gkh + go_ + (size_t)64 * PN);             \
        cp_async16(st_ + 16384 + sw1, gkh + go_ + (size_t)64 * PN + 8);         \
        cp_async16(st_ + 24576 + sw0, gvh + go_ + (size_t)64 * PN);             \
        cp_async16(st_ + 24576 + sw1, gvh + go_ + (size_t)64 * PN + 8);         \
    } while (0)

    {
        const int r = tid >> 1;
        const __nv_bfloat16* gqh = Qh + base + (size_t)(q0 + r) * PN;
        const uint32_t drow = sb + r * 128;
#pragma unroll
        for (int u = 0; u < 4; u++) {
            const int c16 = (tid & 1) * 4 + u;
            const uint32_t sw = (uint32_t)((c16 ^ (r & 7)) << 4);
            cp_async16(drow + sw, gqh + c16 * 8);
        }
    }
    CP_COMMIT();
    LOAD_STAGE(0); CP_COMMIT();
    LOAD_STAGE(1); CP_COMMIT();

    CP_WAIT2();
    __syncthreads();
    uint32_t qfh[4][4];
    {
        const int r = 16 * wid + (lane & 15);
        const uint32_t rowa = sb + r * 128;
#pragma unroll
        for (int t = 0; t < 4; t++) {
            const int c16 = 2 * t + (lane >> 4);
            const uint32_t a = rowa + (uint32_t)((c16 ^ (r & 7)) << 4);
            ldsm_x4(qfh[t], a);
        }
    }

    float l0 = 0.f, l1 = 0.f;
    float o[8][4];
#pragma unroll
    for (int j = 0; j < 8; j++)
#pragma unroll
        for (int v = 0; v < 4; v++) o[j][v] = 0.f;

    const int NIT = PT / 128;   // 16
    for (int it = 0; it < NIT; it++) {
        CP_WAIT1();
        __syncthreads();
        if (it + 2 < NIT) LOAD_STAGE(it + 2);
        CP_COMMIT();
        const uint32_t stg = sb + FLS_QB + (uint32_t)((it % 3) * FLS_STAGE);

#pragma unroll
        for (int sub = 0; sub < 2; sub++) {
            const uint32_t st = stg + (uint32_t)(sub * 16384);

            // ---- S = Qh*Kh  (log2-domain scores; 32 MMAs)
            float s[8][4];
#pragma unroll
            for (int j = 0; j < 8; j++)
#pragma unroll
                for (int v = 0; v < 4; v++) s[j][v] = 0.f;
#pragma unroll
            for (int t = 0; t < 4; t++) {
                uint32_t kbh[4][4];
#pragma unroll
                for (int np = 0; np < 4; np++) {
                    const int row = np * 16 + (lane & 7) + ((lane >> 4) << 3);
                    const int c16 = 2 * t + ((lane >> 3) & 1);
                    const uint32_t a = st + row * 128 + (uint32_t)((c16 ^ (row & 7)) << 4);
                    ldsm_x4(kbh[np], a);
                }
#pragma unroll
                for (int np = 0; np < 4; np++) {
                    mma_bf16(s[2*np],   qfh[t], kbh[np] + 0);
                    mma_bf16(s[2*np+1], qfh[t], kbh[np] + 2);
                }
            }

            // ---- E = 2^s - 1 (small); accumulate l-correction
#pragma unroll
            for (int j = 0; j < 8; j++) {
                s[j][0] = fast_ex2(s[j][0]) - 1.f; s[j][1] = fast_ex2(s[j][1]) - 1.f;
                s[j][2] = fast_ex2(s[j][2]) - 1.f; s[j][3] = fast_ex2(s[j][3]) - 1.f;
                l0 += s[j][0] + s[j][1];
                l1 += s[j][2] + s[j][3];
            }

            // ---- pack E into single-term bf16 A-fragments
            uint32_t pfh[4][4];
#pragma unroll
            for (int kt = 0; kt < 4; kt++) {
                pfh[kt][0] = pack_bf16x2(s[2*kt][0],   s[2*kt][1]);
                pfh[kt][1] = pack_bf16x2(s[2*kt][2],   s[2*kt][3]);
                pfh[kt][2] = pack_bf16x2(s[2*kt+1][0], s[2*kt+1][1]);
                pfh[kt][3] = pack_bf16x2(s[2*kt+1][2], s[2*kt+1][3]);
            }

            // ---- O += E*Vh  (32 MMAs)
#pragma unroll
            for (int kt = 0; kt < 4; kt++) {
                uint32_t vbh[4][4];
#pragma unroll
                for (int np = 0; np < 4; np++) {
                    const int row = 16 * kt + (lane & 15);
                    const int c16 = 2 * np + (lane >> 4);
                    const uint32_t a = st + 8192 + row * 128 +
                                       (uint32_t)((c16 ^ (row & 7)) << 4);
                    ldsm_x4_t(vbh[np], a);
                }
#pragma unroll
                for (int np = 0; np < 4; np++) {
                    mma_bf16(o[2*np],   pfh[kt], vbh[np] + 0);
                    mma_bf16(o[2*np+1], pfh[kt], vbh[np] + 2);
                }
            }
        }
    }

    // ---- final: l = 2048 + sum(E); corr = (E*V)/l (bf16), invl = 1/l
    l0 += __shfl_xor_sync(0xffffffffu, l0, 1);
    l0 += __shfl_xor_sync(0xffffffffu, l0, 2);
    l1 += __shfl_xor_sync(0xffffffffu, l1, 1);
    l1 += __shfl_xor_sync(0xffffffffu, l1, 2);
    const float inv0 = 1.f / (2048.f + l0), inv1 = 1.f / (2048.f + l1);
    const int r0 = q0 + 16 * wid + (lane >> 2);   // t index
    const int c = 2 * (lane & 3);
    if ((lane & 3) == 0) {
        Invl[(size_t)(b * PT + r0) * PH + h]     = inv0;
        Invl[(size_t)(b * PT + r0 + 8) * PH + h] = inv1;
    }
#pragma unroll
    for (int j = 0; j < 8; j++) {
        const int gc = 8 * j + c;
        *(uint32_t*)(Corr + base + (size_t)r0 * PN + gc) =
            pack_bf16x2(o[j][0] * inv0, o[j][1] * inv0);
        *(uint32_t*)(Corr + base + (size_t)(r0 + 8) * PN + gc) =
            pack_bf16x2(o[j][2] * inv1, o[j][3] * inv1);
    }
}

// ---------------- launch -----------------------------------------------------
extern "C" void kernel_launch(void* const* d_in, const int* in_sizes, int n_in,
                              void* d_out, int out_size) {
    const float* x  = (const float*)d_in[0];
    const float* WQ = (const float*)d_in[1];
    const float* bQ = (const float*)d_in[2];
    const float* WK = (const float*)d_in[3];
    const float* bK = (const float*)d_in[4];
    const float* WV = (const float*)d_in[5];
    const float* bV = (const float*)d_in[6];
    const float* WO = (const float*)d_in[7];
    const float* bO = (const float*)d_in[8];
    float* out = (float*)d_out;

    __nv_bfloat16 *xh, *wqh, *wkh, *wvh, *oth;
    __nv_bfloat16 *qh, *kh, *vh, *corr;
    float *xsump, *invl, *w1;
    cudaGetSymbolAddress((void**)&xh,  g_xh);
    cudaGetSymbolAddress((void**)&wqh, g_wqh);
    cudaGetSymbolAddress((void**)&wkh, g_wkh);
    cudaGetSymbolAddress((void**)&wvh, g_wvh);
    cudaGetSymbolAddress((void**)&oth, g_oth);
    cudaGetSymbolAddress((void**)&qh,  g_qh);
    cudaGetSymbolAddress((void**)&kh,  g_kh);
    cudaGetSymbolAddress((void**)&vh,  g_vh);
    cudaGetSymbolAddress((void**)&corr, g_corr);
    cudaGetSymbolAddress((void**)&invl, g_invl);
    cudaGetSymbolAddress((void**)&w1,   g_w1);
    cudaGetSymbolAddress((void**)&xsump, g_xsump);

    cudaFuncSetAttribute(gemm_out, cudaFuncAttributeMaxDynamicSharedMemorySize, GEMM_SMEM);
    cudaFuncSetAttribute(gemm_qkv, cudaFuncAttributeMaxDynamicSharedMemorySize, GEMM_SMEM);
    cudaFuncSetAttribute(flash_mma, cudaFuncAttributeMaxDynamicSharedMemorySize, FLS_SMEM);

    // fused setup: bf16 conversions + WO transpose + x column partial sums
    setup_all<<<15392, 256>>>(x, WQ, WK, WV, WO, xh, wqh, wkh, wvh, oth, xsump);

    // exact sumv (colsum identity) + W1, fused in one kernel (fp32 exact)
    sumv_w1<<<PB * PH, 256>>>(xsump, WV, bV, WO, w1);

    // fused QKV projections (all 1-term); Q pre-scaled by log2(e)/sqrt(Dh)
    gemm_qkv<<<dim3(PN / 128, PM / 128, 3), 256, GEMM_SMEM>>>(
        xh, wqh, wkh, wvh, bQ, bK, bV, qh, kh, vh);

    flash_mma<<<dim3(PT / 128, PB * PH), 256, FLS_SMEM>>>(qh, kh, vh, corr, invl);

    gemm_out<<<dim3(PN / 128, PM / 128), 256, GEMM_SMEM>>>(
        corr, oth, bO, invl, w1, out);
}